// round 1
// baseline (speedup 1.0000x reference)
#include <cuda_runtime.h>
#include <cstdint>

// Problem shape (fixed for this problem instance)
#define B_   16
#define LQ_  2048
#define LK_  2048
#define D_   128

#define BM   128          // q-rows per CTA
#define BN   128          // k-cols per tile
#define SQ   130          // smem stride for Qt  [D][BM+2]
#define SK   132          // smem stride for K/E and V tiles [128][128+4]
#define NTHREADS 256
#define SCALE 0.08838834764831845f   // 1/sqrt(128)

#define OUTE  ((long long)B_ * LQ_ * D_)    //  4,194,304
#define ATTNE ((long long)B_ * LQ_ * LK_)   // 67,108,864

#define SMEM_FLOATS (D_ * SQ + 128 * SK + 128 * SK)
#define SMEM_BYTES  (SMEM_FLOATS * 4)

// -------- device scratch (allocation-free rule: __device__ globals) --------
__device__ float g_linv[B_ * LQ_];
__device__ float g_scr_out[(size_t)B_ * LQ_ * D_];
__device__ float g_scr_attn[(size_t)B_ * LQ_ * LK_];

// -------- packed f32x2 helpers --------
static __device__ __forceinline__ unsigned long long pk2(float lo, float hi) {
    unsigned long long r;
    asm("mov.b64 %0, {%1, %2};" : "=l"(r) : "f"(lo), "f"(hi));
    return r;
}
static __device__ __forceinline__ void upk2(unsigned long long p, float& lo, float& hi) {
    asm("mov.b64 {%0, %1}, %2;" : "=f"(lo), "=f"(hi) : "l"(p));
}
static __device__ __forceinline__ unsigned long long f2fma(unsigned long long a,
                                                           unsigned long long b,
                                                           unsigned long long c) {
    unsigned long long d;
    asm("fma.rn.f32x2 %0, %1, %2, %3;" : "=l"(d) : "l"(a), "l"(b), "l"(c));
    return d;
}

// ===========================================================================
// Fused attention kernel.
//  grid = (LQ/BM, B), block = 256 threads (16 tx col-groups x 16 ty row-groups)
//  Thread micro-tile: 8 rows (4 row-pairs) x 8 cols (two float4 groups at
//  cA=tx*4 and cB=64+tx*4). Accumulators are f32x2 row-pairs.
// ===========================================================================
__global__ __launch_bounds__(NTHREADS, 1)
void attn_fused(const float* __restrict__ q, const float* __restrict__ k,
                const float* __restrict__ v, const int* __restrict__ mask,
                float* __restrict__ out, float* __restrict__ attn)
{
    extern __shared__ float sm[];
    float* Qt = sm;                  // [D][BM]  (transposed, pre-scaled)
    float* KE = sm + D_ * SQ;        // [128][BN] Kt during GEMM1, then Et
    float* Vs = KE + 128 * SK;       // [128][D]

    const int tid  = threadIdx.x;
    const int tx   = tid & 15;
    const int ty   = tid >> 4;
    const int lane = tid & 31;
    const int w    = tid >> 5;

    const int b  = blockIdx.y;
    const int q0 = blockIdx.x * BM;

    const int r0 = ty * 8;           // first of this thread's 8 rows
    const int cA = tx * 4;           // first col group
    const int cB = 64 + tx * 4;      // second col group

    const float* qb = q + ((size_t)b * LQ_ + q0) * D_;
    const float* kb = k + (size_t)b * LK_ * D_;
    const float* vb = v + (size_t)b * LK_ * D_;
    const int*   mb = mask + ((size_t)b * LQ_ + q0) * (size_t)LK_;
    float* attn_b   = attn + ((size_t)b * LQ_ + q0) * (size_t)LK_;
    float* out_b    = out  + ((size_t)b * LQ_ + q0) * (size_t)D_;

    // ---- load Q tile transposed into smem, pre-scaled by 1/sqrt(D) ----
    #pragma unroll
    for (int rr = 0; rr < 16; rr++) {
        const int r = w * 16 + rr;
        const float* qrow = qb + (size_t)r * D_;
        #pragma unroll
        for (int dd = 0; dd < 4; dd++) {
            const int d = lane + 32 * dd;
            Qt[d * SQ + r] = qrow[d] * SCALE;
        }
    }

    // persistent accumulators
    unsigned long long oacc[4][8];
    #pragma unroll
    for (int p = 0; p < 4; p++)
        #pragma unroll
        for (int j = 0; j < 8; j++) oacc[p][j] = 0ULL;

    float lsum[8];
    #pragma unroll
    for (int i = 0; i < 8; i++) lsum[i] = 0.0f;

    for (int t = 0; t < LK_ / BN; t++) {
        const int k0 = t * BN;

        __syncthreads();   // previous GEMM2 done -> KE/Vs reusable

        // ---- load K tile transposed: KE[d][n] ----
        #pragma unroll
        for (int rr = 0; rr < 16; rr++) {
            const int n = w * 16 + rr;
            const float* krow = kb + (size_t)(k0 + n) * D_;
            #pragma unroll
            for (int dd = 0; dd < 4; dd++) {
                const int d = lane + 32 * dd;
                KE[d * SK + n] = krow[d];
            }
        }
        // ---- load V tile straight: Vs[kk][c] ----
        #pragma unroll
        for (int i = 0; i < 16; i++) {
            const int idx = tid * 4 + i * 1024;
            const int kkr = idx >> 7, c = idx & 127;
            *(float4*)&Vs[kkr * SK + c] =
                *(const float4*)&vb[(size_t)(k0 + kkr) * D_ + c];
        }
        // ---- mask bits for this thread's 8x8 fragment (issued early) ----
        unsigned mbits[8];
        #pragma unroll
        for (int i = 0; i < 8; i++) {
            const int4 ma = *(const int4*)&mb[(size_t)(r0 + i) * LK_ + k0 + cA];
            const int4 mc = *(const int4*)&mb[(size_t)(r0 + i) * LK_ + k0 + cB];
            unsigned bits = 0;
            bits |= (ma.x != 0) ? 0x01u : 0u;
            bits |= (ma.y != 0) ? 0x02u : 0u;
            bits |= (ma.z != 0) ? 0x04u : 0u;
            bits |= (ma.w != 0) ? 0x08u : 0u;
            bits |= (mc.x != 0) ? 0x10u : 0u;
            bits |= (mc.y != 0) ? 0x20u : 0u;
            bits |= (mc.z != 0) ? 0x40u : 0u;
            bits |= (mc.w != 0) ? 0x80u : 0u;
            mbits[i] = bits;
        }

        __syncthreads();   // tiles ready

        // ---- GEMM1: S = Qt^T * Kt  (packed f32x2) ----
        unsigned long long acc[4][8];
        #pragma unroll
        for (int p = 0; p < 4; p++)
            #pragma unroll
            for (int j = 0; j < 8; j++) acc[p][j] = 0ULL;

        #pragma unroll 4
        for (int d = 0; d < 128; d++) {
            const float* qtp = Qt + d * SQ + r0;
            unsigned long long aa[4];
            aa[0] = *(const unsigned long long*)(qtp);
            aa[1] = *(const unsigned long long*)(qtp + 2);
            aa[2] = *(const unsigned long long*)(qtp + 4);
            aa[3] = *(const unsigned long long*)(qtp + 6);
            const float4 kv0 = *(const float4*)(KE + d * SK + cA);
            const float4 kv1 = *(const float4*)(KE + d * SK + cB);
            unsigned long long bb[8];
            bb[0] = pk2(kv0.x, kv0.x); bb[1] = pk2(kv0.y, kv0.y);
            bb[2] = pk2(kv0.z, kv0.z); bb[3] = pk2(kv0.w, kv0.w);
            bb[4] = pk2(kv1.x, kv1.x); bb[5] = pk2(kv1.y, kv1.y);
            bb[6] = pk2(kv1.z, kv1.z); bb[7] = pk2(kv1.w, kv1.w);
            #pragma unroll
            for (int p = 0; p < 4; p++)
                #pragma unroll
                for (int j = 0; j < 8; j++)
                    acc[p][j] = f2fma(aa[p], bb[j], acc[p][j]);
        }

        __syncthreads();   // all GEMM1 reads of KE done

        // ---- exp, mask, E -> smem (transposed) + attn gmem, row sums ----
        #pragma unroll
        for (int p = 0; p < 4; p++) {
            #pragma unroll
            for (int j = 0; j < 8; j++) {
                const int colv = (j < 4) ? (cA + j) : (cB + j - 4);
                float s0, s1;
                upk2(acc[p][j], s0, s1);
                const float e0 = ((mbits[2 * p]     >> j) & 1) ? __expf(s0) : 0.0f;
                const float e1 = ((mbits[2 * p + 1] >> j) & 1) ? __expf(s1) : 0.0f;
                lsum[2 * p]     += e0;
                lsum[2 * p + 1] += e1;
                *(unsigned long long*)(KE + colv * SK + r0 + 2 * p) = pk2(e0, e1);
                attn_b[(size_t)(r0 + 2 * p)     * LK_ + k0 + colv] = e0;
                attn_b[(size_t)(r0 + 2 * p + 1) * LK_ + k0 + colv] = e1;
            }
        }

        __syncthreads();   // Et complete

        // ---- GEMM2: out_acc += Et^T * V  (packed f32x2) ----
        #pragma unroll 4
        for (int kk = 0; kk < 128; kk++) {
            const float* etp = KE + kk * SK + r0;
            unsigned long long aa[4];
            aa[0] = *(const unsigned long long*)(etp);
            aa[1] = *(const unsigned long long*)(etp + 2);
            aa[2] = *(const unsigned long long*)(etp + 4);
            aa[3] = *(const unsigned long long*)(etp + 6);
            const float4 vv0 = *(const float4*)(Vs + kk * SK + cA);
            const float4 vv1 = *(const float4*)(Vs + kk * SK + cB);
            unsigned long long bb[8];
            bb[0] = pk2(vv0.x, vv0.x); bb[1] = pk2(vv0.y, vv0.y);
            bb[2] = pk2(vv0.z, vv0.z); bb[3] = pk2(vv0.w, vv0.w);
            bb[4] = pk2(vv1.x, vv1.x); bb[5] = pk2(vv1.y, vv1.y);
            bb[6] = pk2(vv1.z, vv1.z); bb[7] = pk2(vv1.w, vv1.w);
            #pragma unroll
            for (int p = 0; p < 4; p++)
                #pragma unroll
                for (int j = 0; j < 8; j++)
                    oacc[p][j] = f2fma(aa[p], bb[j], oacc[p][j]);
        }
    }

    // ---- reduce row sums across the 16 tx lanes (half-warp) ----
    #pragma unroll
    for (int i = 0; i < 8; i++) {
        #pragma unroll
        for (int off = 1; off < 16; off <<= 1)
            lsum[i] += __shfl_xor_sync(0xFFFFFFFFu, lsum[i], off, 16);
    }
    float linv_r[8];
    #pragma unroll
    for (int i = 0; i < 8; i++) linv_r[i] = 1.0f / lsum[i];

    if (tx == 0) {
        #pragma unroll
        for (int i = 0; i < 8; i++)
            g_linv[(size_t)b * LQ_ + q0 + r0 + i] = linv_r[i];
    }

    // ---- write normalized out ----
    #pragma unroll
    for (int p = 0; p < 4; p++) {
        #pragma unroll
        for (int j = 0; j < 8; j++) {
            const int colv = (j < 4) ? (cA + j) : (cB + j - 4);
            float o0, o1;
            upk2(oacc[p][j], o0, o1);
            out_b[(size_t)(r0 + 2 * p)     * D_ + colv] = o0 * linv_r[2 * p];
            out_b[(size_t)(r0 + 2 * p + 1) * D_ + colv] = o1 * linv_r[2 * p + 1];
        }
    }
}

// ===========================================================================
// Normalize attn in place: attn[row][*] *= 1/l[row]
// ===========================================================================
__global__ void norm_attn(float4* __restrict__ a4)
{
    const unsigned i = blockIdx.x * blockDim.x + threadIdx.x;  // < ATTNE/4
    const float s = g_linv[i >> 9];   // 512 float4 per row of 2048
    float4 a = a4[i];
    a.x *= s; a.y *= s; a.z *= s; a.w *= s;
    a4[i] = a;
}

// ===========================================================================
extern "C" void kernel_launch(void* const* d_in, const int* in_sizes, int n_in,
                              void* d_out, int out_size)
{
    const float* q  = (const float*)d_in[0];
    const float* k  = (const float*)d_in[1];
    const float* v  = (const float*)d_in[2];
    const int*   m  = (const int*)d_in[3];

    float* scr_out  = nullptr;
    float* scr_attn = nullptr;
    cudaGetSymbolAddress((void**)&scr_out,  g_scr_out);
    cudaGetSymbolAddress((void**)&scr_attn, g_scr_attn);

    float* outp;
    float* attnp;
    const long long osz = (long long)out_size;
    if (osz >= OUTE + ATTNE) {           // tuple (out, attn) concatenated
        outp  = (float*)d_out;
        attnp = (float*)d_out + OUTE;
    } else if (osz == ATTNE) {           // attn only
        attnp = (float*)d_out;
        outp  = scr_out;
    } else {                             // out only
        outp  = (float*)d_out;
        attnp = scr_attn;
    }

    cudaFuncSetAttribute(attn_fused,
                         cudaFuncAttributeMaxDynamicSharedMemorySize, SMEM_BYTES);

    dim3 grid(LQ_ / BM, B_);
    attn_fused<<<grid, NTHREADS, SMEM_BYTES>>>(q, k, v, m, outp, attnp);

    const unsigned nblk = (unsigned)(ATTNE / 4 / 256);   // 65536
    norm_attn<<<nblk, 256>>>((float4*)attnp);
}

// round 4
// speedup vs baseline: 1.2375x; 1.2375x over previous
#include <cuda_runtime.h>
#include <cstdint>

// ---------------- problem shape ----------------
#define B_    16
#define LQ_   2048
#define LK_   2048
#define D_    128
#define BM    128
#define BN    64
#define NTILES (LK_ / BN)
#define NTH   256
#define SCALE 0.08838834764831845f   // 1/sqrt(128)

#define OUTE  ((long long)B_ * LQ_ * D_)
#define ATTNE ((long long)B_ * LQ_ * LK_)

// ---------------- smem layout (byte offsets) ----------------
// bf16 tiles with padded strides (pad = 8 bf16 = 16B keeps ldmatrix 16B-aligned
// and makes row stride 17*16B / 9*16B -> conflict-free ldmatrix patterns)
#define QSTR  272u   // 136 bf16 per row
#define KSTR  272u
#define VSTR  272u
#define PSTR  144u   // 72 bf16 per row

#define QH_B  0u
#define QL_B  34816u     // 128*272
#define KH_B  69632u
#define KL_B  87040u     // +64*272
#define VH_B  104448u
#define VL_B  121856u
#define PH_B  139264u
#define PL_B  157696u    // +128*144
#define RS_B  176128u    // 2*128 floats
#define SMEM_BYTES 177152u

// ---------------- device scratch ----------------
__device__ float g_linv[B_ * LQ_];
__device__ float g_scr_out[(size_t)B_ * LQ_ * D_];
__device__ float g_scr_attn[(size_t)B_ * LQ_ * LK_];

// ---------------- helpers ----------------
static __device__ __forceinline__ uint32_t smem_u32(const void* p) {
    uint32_t a;
    asm("{ .reg .u64 t; cvta.to.shared.u64 t, %1; cvt.u32.u64 %0, t; }"
        : "=r"(a) : "l"(p));
    return a;
}
static __device__ __forceinline__ uint32_t fasu(float x) { return __float_as_uint(x); }
static __device__ __forceinline__ float trunch(float x) {
    return __uint_as_float(__float_as_uint(x) & 0xFFFF0000u);
}
// pack {hi16(b) : hi16(a)} -> (a = low element, b = high element)
static __device__ __forceinline__ uint32_t prmt_hi(uint32_t a, uint32_t b) {
    uint32_t r; asm("prmt.b32 %0, %1, %2, 0x7632;" : "=r"(r) : "r"(a), "r"(b));
    return r;
}
// pack bf16x2: result upper = bf16(hi), lower = bf16(lo)
static __device__ __forceinline__ uint32_t cvt2bf(float hi, float lo) {
    uint32_t r; asm("cvt.rn.bf16x2.f32 %0, %1, %2;" : "=r"(r) : "f"(hi), "f"(lo));
    return r;
}

static __device__ __forceinline__ void ldsm_x4(uint32_t r[4], uint32_t a) {
    asm volatile("ldmatrix.sync.aligned.m8n8.x4.shared.b16 {%0,%1,%2,%3}, [%4];"
        : "=r"(r[0]), "=r"(r[1]), "=r"(r[2]), "=r"(r[3]) : "r"(a));
}
static __device__ __forceinline__ void ldsm_x2(uint32_t r[2], uint32_t a) {
    asm volatile("ldmatrix.sync.aligned.m8n8.x2.shared.b16 {%0,%1}, [%2];"
        : "=r"(r[0]), "=r"(r[1]) : "r"(a));
}
static __device__ __forceinline__ void ldsm_x2t(uint32_t r[2], uint32_t a) {
    asm volatile("ldmatrix.sync.aligned.m8n8.x2.trans.shared.b16 {%0,%1}, [%2];"
        : "=r"(r[0]), "=r"(r[1]) : "r"(a));
}
static __device__ __forceinline__ void mma_bf(float c[4], const uint32_t a[4],
                                              const uint32_t b[2]) {
    asm volatile("mma.sync.aligned.m16n8k16.row.col.f32.bf16.bf16.f32 "
        "{%0,%1,%2,%3}, {%4,%5,%6,%7}, {%8,%9}, {%0,%1,%2,%3};"
        : "+f"(c[0]), "+f"(c[1]), "+f"(c[2]), "+f"(c[3])
        : "r"(a[0]), "r"(a[1]), "r"(a[2]), "r"(a[3]), "r"(b[0]), "r"(b[1]));
}

// ===========================================================================
// grid (LQ/BM, B), 256 threads = 8 warps: warp w -> m-slice (w&3)*32,
// n-half (w>>2). 3-pass bf16 hi/lo split on both GEMMs.
// ===========================================================================
__global__ __launch_bounds__(NTH, 1)
void attn_mma(const float* __restrict__ q, const float* __restrict__ k,
              const float* __restrict__ v, const int* __restrict__ mask,
              float* __restrict__ out, float* __restrict__ attn)
{
    extern __shared__ char sm[];
    const uint32_t sb = smem_u32(sm);
    const int tid = threadIdx.x, lane = tid & 31, w = tid >> 5;
    const int mw = w & 3, nh = w >> 2;
    const int m0 = mw * 32;
    const int g = lane >> 2, tg = lane & 3;

    const int b = blockIdx.y, q0 = blockIdx.x * BM;
    const float* qb = q + ((size_t)b * LQ_ + q0) * D_;
    const float* kb = k + (size_t)b * LK_ * D_;
    const float* vb = v + (size_t)b * LK_ * D_;
    const int*   mb = mask + ((size_t)b * LQ_ + q0) * (size_t)LK_;
    float* attn_b   = attn + ((size_t)b * LQ_ + q0) * (size_t)LK_;
    float* out_b    = out  + ((size_t)b * LQ_ + q0) * (size_t)D_;

    // ---- Q load, scale, split hi/lo -> smem ----
    {
        const int row = tid >> 1;
        const int c0  = (tid & 1) * 64;
        const float* qr = qb + (size_t)row * D_ + c0;
        const uint32_t ro = row * QSTR + (uint32_t)c0 * 2;
        #pragma unroll
        for (int j = 0; j < 16; j++) {
            float4 x = *(const float4*)(qr + j * 4);
            x.x *= SCALE; x.y *= SCALE; x.z *= SCALE; x.w *= SCALE;
            *(uint32_t*)(sm + QH_B + ro + j * 8)     = prmt_hi(fasu(x.x), fasu(x.y));
            *(uint32_t*)(sm + QH_B + ro + j * 8 + 4) = prmt_hi(fasu(x.z), fasu(x.w));
            *(uint32_t*)(sm + QL_B + ro + j * 8)     = cvt2bf(x.y - trunch(x.y), x.x - trunch(x.x));
            *(uint32_t*)(sm + QL_B + ro + j * 8 + 4) = cvt2bf(x.w - trunch(x.w), x.z - trunch(x.z));
        }
    }

    // persistent accumulators
    float o[2][8][4];
    #pragma unroll
    for (int mf = 0; mf < 2; mf++)
        #pragma unroll
        for (int nf = 0; nf < 8; nf++)
            #pragma unroll
            for (int i = 0; i < 4; i++) o[mf][nf][i] = 0.0f;
    float rsum[4] = {0.f, 0.f, 0.f, 0.f};

    // lane-constant ldmatrix base addresses
    const uint32_t a_ro = (uint32_t)(m0 + (lane & 15));
    const uint32_t aQh = sb + QH_B + a_ro * QSTR + ((lane >> 4) << 4);
    const uint32_t aQl = sb + QL_B + a_ro * QSTR + ((lane >> 4) << 4);
    const uint32_t aPh = sb + PH_B + a_ro * PSTR + ((lane >> 4) << 4);
    const uint32_t aPl = sb + PL_B + a_ro * PSTR + ((lane >> 4) << 4);
    const uint32_t b_ro = (uint32_t)(nh * 32 + (lane & 7));
    const uint32_t aKh = sb + KH_B + b_ro * KSTR + (((lane >> 3) & 1) << 4);
    const uint32_t aKl = sb + KL_B + b_ro * KSTR + (((lane >> 3) & 1) << 4);
    const uint32_t v_ro = (uint32_t)(lane & 15);
    const uint32_t aVh = sb + VH_B + v_ro * VSTR + (uint32_t)nh * 128u;
    const uint32_t aVl = sb + VL_B + v_ro * VSTR + (uint32_t)nh * 128u;

    for (int t = 0; t < NTILES; t++) {
        __syncthreads();   // previous tile's GEMM2 done; K/V/P reusable

        // ---- K and V tiles: load fp32, split hi/lo bf16 -> smem ----
        {
            const int row = tid >> 2;
            const int c0  = (tid & 3) * 32;
            const uint32_t ro = row * KSTR + (uint32_t)c0 * 2;
            const float* kr = kb + (size_t)(t * BN + row) * D_ + c0;
            const float* vr = vb + (size_t)(t * BN + row) * D_ + c0;
            #pragma unroll
            for (int j = 0; j < 8; j++) {
                float4 x = *(const float4*)(kr + j * 4);
                *(uint32_t*)(sm + KH_B + ro + j * 8)     = prmt_hi(fasu(x.x), fasu(x.y));
                *(uint32_t*)(sm + KH_B + ro + j * 8 + 4) = prmt_hi(fasu(x.z), fasu(x.w));
                *(uint32_t*)(sm + KL_B + ro + j * 8)     = cvt2bf(x.y - trunch(x.y), x.x - trunch(x.x));
                *(uint32_t*)(sm + KL_B + ro + j * 8 + 4) = cvt2bf(x.w - trunch(x.w), x.z - trunch(x.z));
                float4 y = *(const float4*)(vr + j * 4);
                *(uint32_t*)(sm + VH_B + ro + j * 8)     = prmt_hi(fasu(y.x), fasu(y.y));
                *(uint32_t*)(sm + VH_B + ro + j * 8 + 4) = prmt_hi(fasu(y.z), fasu(y.w));
                *(uint32_t*)(sm + VL_B + ro + j * 8)     = cvt2bf(y.y - trunch(y.y), y.x - trunch(y.x));
                *(uint32_t*)(sm + VL_B + ro + j * 8 + 4) = cvt2bf(y.w - trunch(y.w), y.z - trunch(y.z));
            }
        }
        __syncthreads();   // tiles ready

        // ---- GEMM1: S = Qh*Kh + Ql*Kh + Qh*Kl ----
        float s[2][4][4];
        #pragma unroll
        for (int mf = 0; mf < 2; mf++)
            #pragma unroll
            for (int nf = 0; nf < 4; nf++)
                #pragma unroll
                for (int i = 0; i < 4; i++) s[mf][nf][i] = 0.0f;

        #pragma unroll
        for (int ks = 0; ks < 8; ks++) {
            uint32_t ah0[4], ah1[4], al0[4], al1[4], bb[2];
            ldsm_x4(ah0, aQh + ks * 32);
            ldsm_x4(ah1, aQh + 16 * QSTR + ks * 32);
            ldsm_x4(al0, aQl + ks * 32);
            ldsm_x4(al1, aQl + 16 * QSTR + ks * 32);
            #pragma unroll
            for (int nf = 0; nf < 4; nf++) {
                ldsm_x2(bb, aKh + nf * 8 * KSTR + ks * 32);
                mma_bf(s[0][nf], ah0, bb); mma_bf(s[1][nf], ah1, bb);
                mma_bf(s[0][nf], al0, bb); mma_bf(s[1][nf], al1, bb);
                ldsm_x2(bb, aKl + nf * 8 * KSTR + ks * 32);
                mma_bf(s[0][nf], ah0, bb); mma_bf(s[1][nf], ah1, bb);
            }
        }

        // ---- softmax: mask, exp, attn gmem, P hi/lo -> smem ----
        {
            const int k0t = t * BN;
            #pragma unroll
            for (int mf = 0; mf < 2; mf++) {
                const int r0 = m0 + mf * 16 + g;
                const int r1 = r0 + 8;
                #pragma unroll
                for (int nf = 0; nf < 4; nf++) {
                    const int c = nh * 32 + nf * 8 + tg * 2;
                    const int2 mk0 = *(const int2*)(mb + (size_t)r0 * LK_ + k0t + c);
                    const int2 mk1 = *(const int2*)(mb + (size_t)r1 * LK_ + k0t + c);
                    const float e00 = mk0.x ? __expf(s[mf][nf][0]) : 0.0f;
                    const float e01 = mk0.y ? __expf(s[mf][nf][1]) : 0.0f;
                    const float e10 = mk1.x ? __expf(s[mf][nf][2]) : 0.0f;
                    const float e11 = mk1.y ? __expf(s[mf][nf][3]) : 0.0f;
                    rsum[mf * 2]     += e00 + e01;
                    rsum[mf * 2 + 1] += e10 + e11;
                    *(float2*)(attn_b + (size_t)r0 * LK_ + k0t + c) = make_float2(e00, e01);
                    *(float2*)(attn_b + (size_t)r1 * LK_ + k0t + c) = make_float2(e10, e11);
                    *(uint32_t*)(sm + PH_B + r0 * PSTR + c * 2) = prmt_hi(fasu(e00), fasu(e01));
                    *(uint32_t*)(sm + PH_B + r1 * PSTR + c * 2) = prmt_hi(fasu(e10), fasu(e11));
                    *(uint32_t*)(sm + PL_B + r0 * PSTR + c * 2) =
                        cvt2bf(e01 - trunch(e01), e00 - trunch(e00));
                    *(uint32_t*)(sm + PL_B + r1 * PSTR + c * 2) =
                        cvt2bf(e11 - trunch(e11), e10 - trunch(e10));
                }
            }
        }
        __syncthreads();   // P ready

        // ---- GEMM2: O += Ph*Vh + Pl*Vh + Ph*Vl ----
        #pragma unroll
        for (int ks = 0; ks < 4; ks++) {
            uint32_t ph0[4], ph1[4], pl0[4], pl1[4], bb[2];
            ldsm_x4(ph0, aPh + ks * 32);
            ldsm_x4(ph1, aPh + 16 * PSTR + ks * 32);
            ldsm_x4(pl0, aPl + ks * 32);
            ldsm_x4(pl1, aPl + 16 * PSTR + ks * 32);
            #pragma unroll
            for (int nf = 0; nf < 8; nf++) {
                ldsm_x2t(bb, aVh + ks * 16 * VSTR + nf * 16);
                mma_bf(o[0][nf], ph0, bb); mma_bf(o[1][nf], ph1, bb);
                mma_bf(o[0][nf], pl0, bb); mma_bf(o[1][nf], pl1, bb);
                ldsm_x2t(bb, aVl + ks * 16 * VSTR + nf * 16);
                mma_bf(o[0][nf], ph0, bb); mma_bf(o[1][nf], ph1, bb);
            }
        }
    }

    // ---- row-sum reduction: over tg quad, then across the two n-halves ----
    #pragma unroll
    for (int i = 0; i < 4; i++) {
        rsum[i] += __shfl_xor_sync(0xFFFFFFFFu, rsum[i], 1);
        rsum[i] += __shfl_xor_sync(0xFFFFFFFFu, rsum[i], 2);
    }
    float* rs = (float*)(sm + RS_B);
    if (tg == 0) {
        #pragma unroll
        for (int mf = 0; mf < 2; mf++) {
            rs[nh * 128 + m0 + mf * 16 + g]     = rsum[mf * 2];
            rs[nh * 128 + m0 + mf * 16 + g + 8] = rsum[mf * 2 + 1];
        }
    }
    __syncthreads();

    // ---- epilogue: normalize O, write out + 1/l ----
    #pragma unroll
    for (int mf = 0; mf < 2; mf++) {
        const int r0 = m0 + mf * 16 + g, r1 = r0 + 8;
        const float li0 = 1.0f / (rs[r0] + rs[128 + r0]);
        const float li1 = 1.0f / (rs[r1] + rs[128 + r1]);
        if (nh == 0 && tg == 0) {
            g_linv[(size_t)b * LQ_ + q0 + r0] = li0;
            g_linv[(size_t)b * LQ_ + q0 + r1] = li1;
        }
        #pragma unroll
        for (int nf = 0; nf < 8; nf++) {
            const int c = nh * 64 + nf * 8 + tg * 2;
            *(float2*)(out_b + (size_t)r0 * D_ + c) =
                make_float2(o[mf][nf][0] * li0, o[mf][nf][1] * li0);
            *(float2*)(out_b + (size_t)r1 * D_ + c) =
                make_float2(o[mf][nf][2] * li1, o[mf][nf][3] * li1);
        }
    }
}

// ===========================================================================
// Normalize attn in place: attn[row][*] *= 1/l[row]
// ===========================================================================
__global__ void norm_attn(float4* __restrict__ a4)
{
    const unsigned i = blockIdx.x * blockDim.x + threadIdx.x;  // < ATTNE/4
    const float s = g_linv[i >> 9];   // 512 float4 per 2048-row
    float4 a = a4[i];
    a.x *= s; a.y *= s; a.z *= s; a.w *= s;
    a4[i] = a;
}

// ===========================================================================
extern "C" void kernel_launch(void* const* d_in, const int* in_sizes, int n_in,
                              void* d_out, int out_size)
{
    const float* q = (const float*)d_in[0];
    const float* k = (const float*)d_in[1];
    const float* v = (const float*)d_in[2];
    const int*   m = (const int*)d_in[3];

    float* scr_out  = nullptr;
    float* scr_attn = nullptr;
    cudaGetSymbolAddress((void**)&scr_out,  g_scr_out);
    cudaGetSymbolAddress((void**)&scr_attn, g_scr_attn);

    float* outp;
    float* attnp;
    const long long osz = (long long)out_size;
    if (osz >= OUTE + ATTNE) {           // tuple (out, attn) concatenated
        outp  = (float*)d_out;
        attnp = (float*)d_out + OUTE;
    } else if (osz == ATTNE) {
        attnp = (float*)d_out;
        outp  = scr_out;
    } else {
        outp  = (float*)d_out;
        attnp = scr_attn;
    }

    cudaFuncSetAttribute(attn_mma,
                         cudaFuncAttributeMaxDynamicSharedMemorySize, SMEM_BYTES);

    dim3 grid(LQ_ / BM, B_);
    attn_mma<<<grid, NTH, SMEM_BYTES>>>(q, k, v, m, outp, attnp);

    const unsigned nblk = (unsigned)(ATTNE / 4 / 256);
    norm_attn<<<nblk, 256>>>((float4*)attnp);
}

// round 5
// speedup vs baseline: 1.7681x; 1.4288x over previous
#include <cuda_runtime.h>
#include <cstdint>

// ---------------- problem shape ----------------
#define B_    16
#define LQ_   2048
#define LK_   2048
#define D_    128
#define BM    128
#define BN    64
#define NTILES (LK_ / BN)
#define NTH   256
#define SCALE 0.08838834764831845f   // 1/sqrt(128)

#define OUTE  ((long long)B_ * LQ_ * D_)
#define ATTNE ((long long)B_ * LQ_ * LK_)

// ---------------- smem layout (byte offsets) ----------------
#define QSTR  272u
#define KSTR  272u
#define VSTR  272u
#define PSTR  144u

#define QH_B  0u
#define QL_B  34816u
#define STG0  69632u          // stage: K hi/lo, later aliased by P hi/lo
#define STG_SZ 36864u
#define KH_S  0u
#define KL_S  17408u
#define PH_S  0u
#define PL_S  18432u
#define VB0   143360u         // V buffers
#define VB_SZ 34816u
#define VH_S  0u
#define VL_S  17408u
#define RS_B  212992u
#define SMEM_BYTES 214016u

// ---------------- device scratch ----------------
#define NU32  2097152u        // B*LK*D/2  (u32 per hi/lo array)
#define NF4   1048576u        // B*LK*D/4
__device__ uint32_t g_kh[NU32];
__device__ uint32_t g_kl[NU32];
__device__ uint32_t g_vh[NU32];
__device__ uint32_t g_vl[NU32];
__device__ uint32_t g_mbits[NU32];   // B*LQ*LK/32
__device__ float g_linv[B_ * LQ_];
__device__ float g_scr_out[(size_t)B_ * LQ_ * D_];
__device__ float g_scr_attn[(size_t)B_ * LQ_ * LK_];

// ---------------- helpers ----------------
static __device__ __forceinline__ uint32_t smem_u32(const void* p) {
    uint32_t a;
    asm("{ .reg .u64 t; cvta.to.shared.u64 t, %1; cvt.u32.u64 %0, t; }"
        : "=r"(a) : "l"(p));
    return a;
}
static __device__ __forceinline__ uint32_t fasu(float x) { return __float_as_uint(x); }
static __device__ __forceinline__ float trunch(float x) {
    return __uint_as_float(__float_as_uint(x) & 0xFFFF0000u);
}
static __device__ __forceinline__ uint32_t prmt_hi(uint32_t a, uint32_t b) {
    uint32_t r; asm("prmt.b32 %0, %1, %2, 0x7632;" : "=r"(r) : "r"(a), "r"(b));
    return r;
}
static __device__ __forceinline__ uint32_t cvt2bf(float hi, float lo) {
    uint32_t r; asm("cvt.rn.bf16x2.f32 %0, %1, %2;" : "=r"(r) : "f"(hi), "f"(lo));
    return r;
}
static __device__ __forceinline__ void cpa16(uint32_t dst, const void* src) {
    asm volatile("cp.async.cg.shared.global [%0], [%1], 16;" :: "r"(dst), "l"(src));
}
#define CP_COMMIT() asm volatile("cp.async.commit_group;" ::: "memory")
#define CP_WAIT0()  asm volatile("cp.async.wait_group 0;" ::: "memory")

static __device__ __forceinline__ void ldsm_x4(uint32_t r[4], uint32_t a) {
    asm volatile("ldmatrix.sync.aligned.m8n8.x4.shared.b16 {%0,%1,%2,%3}, [%4];"
        : "=r"(r[0]), "=r"(r[1]), "=r"(r[2]), "=r"(r[3]) : "r"(a));
}
static __device__ __forceinline__ void ldsm_x2(uint32_t r[2], uint32_t a) {
    asm volatile("ldmatrix.sync.aligned.m8n8.x2.shared.b16 {%0,%1}, [%2];"
        : "=r"(r[0]), "=r"(r[1]) : "r"(a));
}
static __device__ __forceinline__ void ldsm_x2t(uint32_t r[2], uint32_t a) {
    asm volatile("ldmatrix.sync.aligned.m8n8.x2.trans.shared.b16 {%0,%1}, [%2];"
        : "=r"(r[0]), "=r"(r[1]) : "r"(a));
}
static __device__ __forceinline__ void mma_bf(float c[4], const uint32_t a[4],
                                              const uint32_t b[2]) {
    asm volatile("mma.sync.aligned.m16n8k16.row.col.f32.bf16.bf16.f32 "
        "{%0,%1,%2,%3}, {%4,%5,%6,%7}, {%8,%9}, {%0,%1,%2,%3};"
        : "+f"(c[0]), "+f"(c[1]), "+f"(c[2]), "+f"(c[3])
        : "r"(a[0]), "r"(a[1]), "r"(a[2]), "r"(a[3]), "r"(b[0]), "r"(b[1]));
}

// ===========================================================================
// Prepass: K,V fp32 -> bf16 hi/lo packed; mask int32 -> bit-packed.
// ===========================================================================
__global__ __launch_bounds__(256)
void prep(const float4* __restrict__ kf, const float4* __restrict__ vf,
          const int4* __restrict__ m)
{
    const uint32_t i = blockIdx.x * 256u + threadIdx.x;
    if (i < 2u * NF4) {
        const bool isK = i < NF4;
        const uint32_t j = isK ? i : i - NF4;
        const float4 x = (isK ? kf : vf)[j];
        uint32_t* H = isK ? g_kh : g_vh;
        uint32_t* L = isK ? g_kl : g_vl;
        H[2*j]   = prmt_hi(fasu(x.x), fasu(x.y));
        H[2*j+1] = prmt_hi(fasu(x.z), fasu(x.w));
        L[2*j]   = cvt2bf(x.y - trunch(x.y), x.x - trunch(x.x));
        L[2*j+1] = cvt2bf(x.w - trunch(x.w), x.z - trunch(x.z));
    } else {
        const uint32_t j = i - 2u * NF4;     // word index < NU32
        const int4* mp = m + (size_t)j * 8;
        uint32_t wb = 0;
        #pragma unroll
        for (int c = 0; c < 8; c++) {
            const int4 mm = mp[c];
            wb |= (mm.x ? 1u : 0u) << (c * 4);
            wb |= (mm.y ? 1u : 0u) << (c * 4 + 1);
            wb |= (mm.z ? 1u : 0u) << (c * 4 + 2);
            wb |= (mm.w ? 1u : 0u) << (c * 4 + 3);
        }
        g_mbits[j] = wb;
    }
}

// ===========================================================================
// Main fused kernel: cp.async double-buffered K/V (pre-packed bf16 hi/lo),
// P aliases consumed K stage, mask from bit-packed words in registers.
// ===========================================================================
__global__ __launch_bounds__(NTH, 1)
void attn_mma(const float* __restrict__ q, const int* __restrict__ dummy,
              float* __restrict__ out, float* __restrict__ attn)
{
    extern __shared__ char sm[];
    const uint32_t sb = smem_u32(sm);
    const int tid = threadIdx.x, lane = tid & 31, w = tid >> 5;
    const int mw_ = w & 3, nh = w >> 2;
    const int m0 = mw_ * 32;
    const int g = lane >> 2, tg = lane & 3;

    const int b = blockIdx.y, q0 = blockIdx.x * BM;
    const float* qb = q + ((size_t)b * LQ_ + q0) * D_;
    float* attn_b   = attn + ((size_t)b * LQ_ + q0) * (size_t)LK_;
    float* out_b    = out  + ((size_t)b * LQ_ + q0) * (size_t)D_;

    // cp.async source/dst chunk mapping (4 chunks per thread per array)
    const int c_row = tid >> 4;          // 0..15 base rows (x4 strided below)
    const int c_col = tid & 15;          // 16B chunk within row
    // per-iteration: rows c_row + 16*i? Simpler: id = tid + i*256.

    // ---- prolog: issue K[0],V[0] loads ----
    {
        const size_t rb = (size_t)b * LK_;   // + t*BN + row
        #pragma unroll
        for (int i = 0; i < 4; i++) {
            const int id = tid + i * 256;
            const int row = id >> 4, cc = id & 15;
            const size_t so = (rb + row) * 64 + cc * 4;
            const uint32_t d_off = row * KSTR + cc * 16;
            cpa16(sb + STG0 + KH_S + d_off, g_kh + so);
            cpa16(sb + STG0 + KL_S + d_off, g_kl + so);
            cpa16(sb + VB0 + VH_S + d_off, g_vh + so);
            cpa16(sb + VB0 + VL_S + d_off, g_vl + so);
        }
        CP_COMMIT();
    }

    // ---- Q load, scale, split hi/lo -> smem ----
    {
        const int row = tid >> 1;
        const int c0  = (tid & 1) * 64;
        const float* qr = qb + (size_t)row * D_ + c0;
        const uint32_t ro = row * QSTR + (uint32_t)c0 * 2;
        #pragma unroll
        for (int j = 0; j < 16; j++) {
            float4 x = *(const float4*)(qr + j * 4);
            x.x *= SCALE; x.y *= SCALE; x.z *= SCALE; x.w *= SCALE;
            *(uint32_t*)(sm + QH_B + ro + j * 8)     = prmt_hi(fasu(x.x), fasu(x.y));
            *(uint32_t*)(sm + QH_B + ro + j * 8 + 4) = prmt_hi(fasu(x.z), fasu(x.w));
            *(uint32_t*)(sm + QL_B + ro + j * 8)     = cvt2bf(x.y - trunch(x.y), x.x - trunch(x.x));
            *(uint32_t*)(sm + QL_B + ro + j * 8 + 4) = cvt2bf(x.w - trunch(x.w), x.z - trunch(x.z));
        }
    }

    // persistent accumulators
    float o[2][8][4];
    #pragma unroll
    for (int mf = 0; mf < 2; mf++)
        #pragma unroll
        for (int nf = 0; nf < 8; nf++)
            #pragma unroll
            for (int i = 0; i < 4; i++) o[mf][nf][i] = 0.0f;
    float rsum[4] = {0.f, 0.f, 0.f, 0.f};

    // lane-constant address offsets
    const uint32_t a_ro = (uint32_t)(m0 + (lane & 15));
    const uint32_t aQh = sb + QH_B + a_ro * QSTR + ((lane >> 4) << 4);
    const uint32_t aQl = sb + QL_B + a_ro * QSTR + ((lane >> 4) << 4);
    const uint32_t oP  = PH_S + a_ro * PSTR + ((lane >> 4) << 4);   // + stage base
    const uint32_t b_ro = (uint32_t)(nh * 32 + (lane & 7));
    const uint32_t oK  = KH_S + b_ro * KSTR + (((lane >> 3) & 1) << 4);
    const uint32_t v_ro = (uint32_t)(lane & 15);
    const uint32_t oV  = VH_S + v_ro * VSTR + (uint32_t)nh * 128u;

    // mask word row indices for this thread
    const size_t mrow_base = ((size_t)b * LQ_ + q0) * 64u;   // 64 words per row
    const int r00 = m0 + g, r10 = m0 + 16 + g;

    for (int t = 0; t < NTILES; t++) {
        const uint32_t stg = sb + STG0 + (uint32_t)(t & 1) * STG_SZ;
        const uint32_t vbs = sb + VB0 + (uint32_t)(t & 1) * VB_SZ;

        CP_WAIT0();
        __syncthreads();      // K[t],V[t] ready; stage (t+1)&1 and vb (t+1)&1 free

        // ---- issue loads for tile t+1 (hidden under this tile's compute) ----
        if (t + 1 < NTILES) {
            const uint32_t stg2 = sb + STG0 + (uint32_t)((t + 1) & 1) * STG_SZ;
            const uint32_t vbs2 = sb + VB0 + (uint32_t)((t + 1) & 1) * VB_SZ;
            const size_t rb = (size_t)b * LK_ + (t + 1) * BN;
            #pragma unroll
            for (int i = 0; i < 4; i++) {
                const int id = tid + i * 256;
                const int row = id >> 4, cc = id & 15;
                const size_t so = (rb + row) * 64 + cc * 4;
                const uint32_t d_off = row * KSTR + cc * 16;
                cpa16(stg2 + KH_S + d_off, g_kh + so);
                cpa16(stg2 + KL_S + d_off, g_kl + so);
                cpa16(vbs2 + VH_S + d_off, g_vh + so);
                cpa16(vbs2 + VL_S + d_off, g_vl + so);
            }
        }
        CP_COMMIT();

        // ---- mask words -> registers (in flight during GEMM1) ----
        uint32_t mwr[4];
        mwr[0] = g_mbits[mrow_base + (size_t)r00 * 64 + t * 2 + nh];
        mwr[1] = g_mbits[mrow_base + (size_t)(r00 + 8) * 64 + t * 2 + nh];
        mwr[2] = g_mbits[mrow_base + (size_t)r10 * 64 + t * 2 + nh];
        mwr[3] = g_mbits[mrow_base + (size_t)(r10 + 8) * 64 + t * 2 + nh];

        // ---- GEMM1: S = Qh*Kh + Ql*Kh + Qh*Kl ----
        float s[2][4][4];
        #pragma unroll
        for (int mf = 0; mf < 2; mf++)
            #pragma unroll
            for (int nf = 0; nf < 4; nf++)
                #pragma unroll
                for (int i = 0; i < 4; i++) s[mf][nf][i] = 0.0f;

        const uint32_t aKh = stg + oK, aKl = stg + (KL_S - KH_S) + oK;
        #pragma unroll
        for (int ks = 0; ks < 8; ks++) {
            uint32_t ah0[4], ah1[4], al0[4], al1[4], bb[2];
            ldsm_x4(ah0, aQh + ks * 32);
            ldsm_x4(ah1, aQh + 16 * QSTR + ks * 32);
            ldsm_x4(al0, aQl + ks * 32);
            ldsm_x4(al1, aQl + 16 * QSTR + ks * 32);
            #pragma unroll
            for (int nf = 0; nf < 4; nf++) {
                ldsm_x2(bb, aKh + nf * 8 * KSTR + ks * 32);
                mma_bf(s[0][nf], ah0, bb); mma_bf(s[1][nf], ah1, bb);
                mma_bf(s[0][nf], al0, bb); mma_bf(s[1][nf], al1, bb);
                ldsm_x2(bb, aKl + nf * 8 * KSTR + ks * 32);
                mma_bf(s[0][nf], ah0, bb); mma_bf(s[1][nf], ah1, bb);
            }
        }
        __syncthreads();     // all warps done reading K[t]; stage reusable as P

        // ---- softmax: mask bits, exp, attn gmem, P hi/lo -> stage smem ----
        {
            const int k0t = t * BN;
            #pragma unroll
            for (int mf = 0; mf < 2; mf++) {
                const int r0 = m0 + mf * 16 + g;
                const int r1 = r0 + 8;
                const uint32_t w0 = mwr[mf * 2], w1 = mwr[mf * 2 + 1];
                #pragma unroll
                for (int nf = 0; nf < 4; nf++) {
                    const int c = nh * 32 + nf * 8 + tg * 2;
                    const uint32_t pos = (uint32_t)(nf * 8 + tg * 2);
                    const float e00 = ((w0 >> pos) & 1u) ? __expf(s[mf][nf][0]) : 0.0f;
                    const float e01 = ((w0 >> (pos + 1)) & 1u) ? __expf(s[mf][nf][1]) : 0.0f;
                    const float e10 = ((w1 >> pos) & 1u) ? __expf(s[mf][nf][2]) : 0.0f;
                    const float e11 = ((w1 >> (pos + 1)) & 1u) ? __expf(s[mf][nf][3]) : 0.0f;
                    rsum[mf * 2]     += e00 + e01;
                    rsum[mf * 2 + 1] += e10 + e11;
                    *(float2*)(attn_b + (size_t)r0 * LK_ + k0t + c) = make_float2(e00, e01);
                    *(float2*)(attn_b + (size_t)r1 * LK_ + k0t + c) = make_float2(e10, e11);
                    *(uint32_t*)((char*)sm + (stg - sb) + PH_S + r0 * PSTR + c * 2) =
                        prmt_hi(fasu(e00), fasu(e01));
                    *(uint32_t*)((char*)sm + (stg - sb) + PH_S + r1 * PSTR + c * 2) =
                        prmt_hi(fasu(e10), fasu(e11));
                    *(uint32_t*)((char*)sm + (stg - sb) + PL_S + r0 * PSTR + c * 2) =
                        cvt2bf(e01 - trunch(e01), e00 - trunch(e00));
                    *(uint32_t*)((char*)sm + (stg - sb) + PL_S + r1 * PSTR + c * 2) =
                        cvt2bf(e11 - trunch(e11), e10 - trunch(e10));
                }
            }
        }
        __syncthreads();     // P ready

        // ---- GEMM2: O += Ph*Vh + Pl*Vh + Ph*Vl ----
        const uint32_t aPh = stg + oP, aPl = stg + (PL_S - PH_S) + oP;
        const uint32_t aVh = vbs + oV, aVl = vbs + (VL_S - VH_S) + oV;
        #pragma unroll
        for (int ks = 0; ks < 4; ks++) {
            uint32_t ph0[4], ph1[4], pl0[4], pl1[4], bb[2];
            ldsm_x4(ph0, aPh + ks * 32);
            ldsm_x4(ph1, aPh + 16 * PSTR + ks * 32);
            ldsm_x4(pl0, aPl + ks * 32);
            ldsm_x4(pl1, aPl + 16 * PSTR + ks * 32);
            #pragma unroll
            for (int nf = 0; nf < 8; nf++) {
                ldsm_x2t(bb, aVh + ks * 16 * VSTR + nf * 16);
                mma_bf(o[0][nf], ph0, bb); mma_bf(o[1][nf], ph1, bb);
                mma_bf(o[0][nf], pl0, bb); mma_bf(o[1][nf], pl1, bb);
                ldsm_x2t(bb, aVl + ks * 16 * VSTR + nf * 16);
                mma_bf(o[0][nf], ph0, bb); mma_bf(o[1][nf], ph1, bb);
            }
        }
    }

    // ---- row-sum reduction ----
    #pragma unroll
    for (int i = 0; i < 4; i++) {
        rsum[i] += __shfl_xor_sync(0xFFFFFFFFu, rsum[i], 1);
        rsum[i] += __shfl_xor_sync(0xFFFFFFFFu, rsum[i], 2);
    }
    float* rs = (float*)(sm + RS_B);
    if (tg == 0) {
        #pragma unroll
        for (int mf = 0; mf < 2; mf++) {
            rs[nh * 128 + m0 + mf * 16 + g]     = rsum[mf * 2];
            rs[nh * 128 + m0 + mf * 16 + g + 8] = rsum[mf * 2 + 1];
        }
    }
    __syncthreads();

    // ---- epilogue: normalize O, write out + 1/l ----
    #pragma unroll
    for (int mf = 0; mf < 2; mf++) {
        const int r0 = m0 + mf * 16 + g, r1 = r0 + 8;
        const float li0 = 1.0f / (rs[r0] + rs[128 + r0]);
        const float li1 = 1.0f / (rs[r1] + rs[128 + r1]);
        if (nh == 0 && tg == 0) {
            g_linv[(size_t)b * LQ_ + q0 + r0] = li0;
            g_linv[(size_t)b * LQ_ + q0 + r1] = li1;
        }
        #pragma unroll
        for (int nf = 0; nf < 8; nf++) {
            const int c = nh * 64 + nf * 8 + tg * 2;
            *(float2*)(out_b + (size_t)r0 * D_ + c) =
                make_float2(o[mf][nf][0] * li0, o[mf][nf][1] * li0);
            *(float2*)(out_b + (size_t)r1 * D_ + c) =
                make_float2(o[mf][nf][2] * li1, o[mf][nf][3] * li1);
        }
    }
}

// ===========================================================================
__global__ void norm_attn(float4* __restrict__ a4)
{
    const unsigned i = blockIdx.x * blockDim.x + threadIdx.x;
    const float s = g_linv[i >> 9];
    float4 a = a4[i];
    a.x *= s; a.y *= s; a.z *= s; a.w *= s;
    a4[i] = a;
}

// ===========================================================================
extern "C" void kernel_launch(void* const* d_in, const int* in_sizes, int n_in,
                              void* d_out, int out_size)
{
    const float* q = (const float*)d_in[0];
    const float* k = (const float*)d_in[1];
    const float* v = (const float*)d_in[2];
    const int*   m = (const int*)d_in[3];

    float* scr_out  = nullptr;
    float* scr_attn = nullptr;
    cudaGetSymbolAddress((void**)&scr_out,  g_scr_out);
    cudaGetSymbolAddress((void**)&scr_attn, g_scr_attn);

    float* outp;
    float* attnp;
    const long long osz = (long long)out_size;
    if (osz >= OUTE + ATTNE) {
        outp  = (float*)d_out;
        attnp = (float*)d_out + OUTE;
    } else if (osz == ATTNE) {
        attnp = (float*)d_out;
        outp  = scr_out;
    } else {
        outp  = (float*)d_out;
        attnp = scr_attn;
    }

    // prepass: 2*NF4 f4-convert threads + NU32 mask-pack threads
    const unsigned pblk = (2u * NF4 + NU32) / 256u;
    prep<<<pblk, 256>>>((const float4*)k, (const float4*)v, (const int4*)m);

    cudaFuncSetAttribute(attn_mma,
                         cudaFuncAttributeMaxDynamicSharedMemorySize, SMEM_BYTES);
    dim3 grid(LQ_ / BM, B_);
    attn_mma<<<grid, NTH, SMEM_BYTES>>>(q, m, outp, attnp);

    const unsigned nblk = (unsigned)(ATTNE / 4 / 256);
    norm_attn<<<nblk, 256>>>((float4*)attnp);
}